// round 14
// baseline (speedup 1.0000x reference)
#include <cuda_runtime.h>
#include <cstdint>
#include <cstddef>

typedef unsigned long long ull;

#define B_DIM 4096
#define L_DIM 64
#define D_EMB 256
#define H_DIM 20
#define R_TOT (B_DIM * L_DIM)  // 262144 rows

// proj tiling: 128-thread blocks, 4 warps, 64 rows/warp (2 rows/thread)
#define P_THREADS 128
#define P_WARPS 4
#define P_RPW 64
#define P_RPB 256          // rows per block
#define P_XPAD 20          // floats per staged row (2 x 8-float halves + 4 pad)
#define XBUF_WARP (P_RPW * P_XPAD)  // 1280 floats per warp

// ---------------- persistent device scratch (no runtime allocation) ----------
__device__ float g_qs[R_TOT * H_DIM];          // 21 MB
__device__ float g_ks[R_TOT * H_DIM];          // 21 MB
__device__ float g_vs[R_TOT * H_DIM];          // 21 MB
__device__ float g_kvs[L_DIM * H_DIM * H_DIM]; // 25600
__device__ float g_ks_sum[L_DIM * H_DIM];      // 1280
__device__ float g_vs_sum[L_DIM * H_DIM];      // 1280
__device__ float g_sums[4];                    // sum_q, ssq_q, sum_k, ssq_k

// ---------------- packed fp32x2 helpers (Blackwell FFMA2) --------------------
__device__ __forceinline__ ull pack2(float lo, float hi) {
    ull r;
    asm("mov.b64 %0, {%1,%2};" : "=l"(r) : "f"(lo), "f"(hi));
    return r;
}
__device__ __forceinline__ float2 unpack2(ull v) {
    float2 f;
    asm("mov.b64 {%0,%1}, %2;" : "=f"(f.x), "=f"(f.y) : "l"(v));
    return f;
}
__device__ __forceinline__ void fma2(ull& d, ull a, ull b) {
    asm("fma.rn.f32x2 %0, %1, %2, %0;" : "+l"(d) : "l"(a), "l"(b));
}

// ---------------- kernel 0: clear reduction accumulators ---------------------
__global__ void zero_kernel() {
    int i = blockIdx.x * blockDim.x + threadIdx.x;
    if (i < L_DIM * H_DIM * H_DIM) g_kvs[i] = 0.0f;
    if (i < L_DIM * H_DIM) { g_ks_sum[i] = 0.0f; g_vs_sum[i] = 0.0f; }
    if (i < 4) g_sums[i] = 0.0f;
}

// ---------------- kernel 1: projection [R,256] x [256,20] + b ----------------
// 128 threads/block, 5 blocks/SM (20 warps). 2 rows/thread; 8-k half-chunk
// pipeline with 4xfloat4 register prefetch; per-warp SMEM staging rows hold
// two 8-float halves used ping-pong; weights broadcast via LDS.128 pairs.
__global__ void __launch_bounds__(P_THREADS, 5) proj_kernel(
    const float* __restrict__ in, const float* __restrict__ W,
    const float* __restrict__ bias, float* __restrict__ outp, int sumsBase) {
    extern __shared__ char smraw[];
    ull* Ws2 = (ull*)smraw;                      // 2560 ull = 20480 B
    float* bs = (float*)(smraw + 20480);         // 20 floats (pad to 128)
    float* xbuf = (float*)(smraw + 20608);       // 4 * 1280 floats = 20480 B

    int tid = threadIdx.x;
    int w = tid >> 5, lane = tid & 31;

    const ull* W64 = (const ull*)W;
    for (int i = tid; i < D_EMB * H_DIM / 2; i += P_THREADS) Ws2[i] = W64[i];
    if (tid < H_DIM) bs[tid] = bias[tid];
    __syncthreads();

    size_t rowBase = (size_t)blockIdx.x * P_RPB + (size_t)w * P_RPW;
    const float* src = in + rowBase * D_EMB;
    float* xw = xbuf + w * XBUF_WARP;

    // lane -> 4 segments of 16B per 8-k half: s = i*32+lane, row=s>>1, c4=s&1
    int seg_row[4], seg_c4[4];
#pragma unroll
    for (int i = 0; i < 4; i++) {
        int s = i * 32 + lane;
        seg_row[i] = s >> 1;
        seg_c4[i] = s & 1;
    }

    ull acc[2][10];
#pragma unroll
    for (int r = 0; r < 2; r++)
#pragma unroll
        for (int j = 0; j < 10; j++) acc[r][j] = pack2(bs[2 * j], bs[2 * j + 1]);

    // prologue: prefetch half-chunk 0 into registers
    float4 pf[4];
#pragma unroll
    for (int i = 0; i < 4; i++)
        pf[i] = *(const float4*)(src + seg_row[i] * D_EMB + seg_c4[i] * 4);

#pragma unroll 1
    for (int hc = 0; hc < 32; hc++) {  // 32 half-chunks of 8 k
        int slot = hc & 1;             // which 8-float half of the padded row
        __syncwarp(0xffffffffu);       // readers of this slot (iter hc-2) done
#pragma unroll
        for (int i = 0; i < 4; i++)
            *(float4*)&xw[seg_row[i] * P_XPAD + slot * 8 + seg_c4[i] * 4] = pf[i];
        __syncwarp(0xffffffffu);       // staged data visible warp-wide

        // prefetch NEXT half-chunk (LDG latency overlaps compute below)
        if (hc < 31) {
            int koff = (hc + 1) * 8;
#pragma unroll
            for (int i = 0; i < 4; i++)
                pf[i] = *(const float4*)(src + seg_row[i] * D_EMB + koff +
                                         seg_c4[i] * 4);
        }

        // compute this 8-k half
#pragma unroll
        for (int kk4 = 0; kk4 < 2; kk4++) {
            float4 xa = *(const float4*)&xw[lane * P_XPAD + slot * 8 + kk4 * 4];
            float4 xb =
                *(const float4*)&xw[(lane + 32) * P_XPAD + slot * 8 + kk4 * 4];
            const float* fa = (const float*)&xa;
            const float* fb = (const float*)&xb;
#pragma unroll
            for (int q = 0; q < 4; q++) {
                int k = hc * 8 + kk4 * 4 + q;
                const ulonglong2* wq = (const ulonglong2*)&Ws2[k * 10];
                ull xxa = pack2(fa[q], fa[q]);
                ull xxb = pack2(fb[q], fb[q]);
#pragma unroll
                for (int j2 = 0; j2 < 5; j2++) {
                    ulonglong2 t = wq[j2];  // broadcast LDS.128
                    fma2(acc[0][2 * j2], xxa, t.x);
                    fma2(acc[0][2 * j2 + 1], xxa, t.y);
                    fma2(acc[1][2 * j2], xxb, t.x);
                    fma2(acc[1][2 * j2 + 1], xxb, t.y);
                }
            }
        }
    }

    float s1 = 0.0f, s2 = 0.0f;
#pragma unroll
    for (int r = 0; r < 2; r++) {
        float o[H_DIM];
#pragma unroll
        for (int j = 0; j < 10; j++) {
            float2 f = unpack2(acc[r][j]);
            o[2 * j] = f.x;
            o[2 * j + 1] = f.y;
        }
        size_t row = rowBase + lane + 32 * r;
        float4* orow = (float4*)(outp + row * H_DIM);  // 80B rows, 16B aligned
        orow[0] = make_float4(o[0], o[1], o[2], o[3]);
        orow[1] = make_float4(o[4], o[5], o[6], o[7]);
        orow[2] = make_float4(o[8], o[9], o[10], o[11]);
        orow[3] = make_float4(o[12], o[13], o[14], o[15]);
        orow[4] = make_float4(o[16], o[17], o[18], o[19]);
        if (sumsBase >= 0) {
#pragma unroll
            for (int h = 0; h < H_DIM; h++) {
                s1 += o[h];
                s2 = fmaf(o[h], o[h], s2);
            }
        }
    }

    if (sumsBase >= 0) {
#pragma unroll
        for (int off = 16; off >= 1; off >>= 1) {
            s1 += __shfl_xor_sync(0xffffffffu, s1, off);
            s2 += __shfl_xor_sync(0xffffffffu, s2, off);
        }
        if (lane == 0) {
            atomicAdd(&g_sums[sumsBase], s1);
            atomicAdd(&g_sums[sumsBase + 1], s2);
        }
    }
}

// ---------------- kernel 2: kvs[l] = ks[:,l,:]^T @ vs[:,l,:]  (+ ks/vs sums) -
__global__ __launch_bounds__(512) void kvs_kernel() {
    __shared__ float ks_s[32 * H_DIM];
    __shared__ float vs_s[32 * H_DIM];

    int tid = threadIdx.x;
    int l = blockIdx.y;
    int n0 = blockIdx.x * 256;
    int m = tid / H_DIM, d = tid % H_DIM;
    bool active = tid < H_DIM * H_DIM;

    float acc = 0.0f, sk = 0.0f, sv = 0.0f;

    for (int nb = 0; nb < 256; nb += 32) {
        __syncthreads();
        for (int i = tid; i < 32 * H_DIM; i += 512) {
            int rr = i / H_DIM, mm = i % H_DIM;
            size_t base = ((size_t)(n0 + nb + rr) * L_DIM + l) * H_DIM + mm;
            ks_s[i] = g_ks[base];
            vs_s[i] = g_vs[base];
        }
        __syncthreads();
        if (active) {
#pragma unroll
            for (int i = 0; i < 32; i++) {
                float kv = ks_s[i * H_DIM + m];
                float vv = vs_s[i * H_DIM + d];
                acc = fmaf(kv, vv, acc);
                if (d == 0) sk += kv;
                if (m == 0) sv += vv;
            }
        }
    }

    if (active) {
        atomicAdd(&g_kvs[(l * H_DIM + m) * H_DIM + d], acc);
        if (d == 0) atomicAdd(&g_ks_sum[l * H_DIM + m], sk);
        if (m == 0) atomicAdd(&g_vs_sum[l * H_DIM + d], sv);
    }
}

// ---------------- kernel 4: per-row epilogue + final [20]x[20,256] GEMM ------
__global__ __launch_bounds__(256, 2) void final_kernel(
    const float* __restrict__ Wp, const float* __restrict__ bp,
    float* __restrict__ out) {
    __shared__ float attn_s[256 * H_DIM];   // 20 KB
    __shared__ ull kvs2[H_DIM * H_DIM / 2]; // 200
    __shared__ float kss[H_DIM], vss[H_DIM];
    __shared__ float sc_scale;

    int tid = threadIdx.x;
    int w = tid >> 5, lane = tid & 31;
    int l = blockIdx.y;
    int n0 = blockIdx.x * 256;

    int half = w & 1;
    const ulonglong2* Wp128 = (const ulonglong2*)Wp;
    ull wx[H_DIM], wy[H_DIM];
#pragma unroll
    for (int h = 0; h < H_DIM; h++) {
        ulonglong2 t = Wp128[h * 64 + half * 32 + lane];
        wx[h] = t.x;
        wy[h] = t.y;
    }
    ulonglong2 bpr = ((const ulonglong2*)bp)[half * 32 + lane];

    if (tid < H_DIM * H_DIM / 2)
        kvs2[tid] = ((const ull*)g_kvs)[l * (H_DIM * H_DIM / 2) + tid];
    if (tid < H_DIM) {
        kss[tid] = g_ks_sum[l * H_DIM + tid];
        vss[tid] = g_vs_sum[l * H_DIM + tid];
    }
    if (tid == 0) {
        bool cond = (g_sums[0] != 0.0f) && (g_sums[2] != 0.0f);
        sc_scale = cond ? 1.0f / (sqrtf(g_sums[1]) * sqrtf(g_sums[3])) : 1.0f;
    }
    __syncthreads();

    {
        float scale = sc_scale;
        size_t n = (size_t)(n0 + tid);
        size_t r = n * L_DIM + l;
        const float4* qrow = (const float4*)(g_qs + r * H_DIM);
        float q[H_DIM];
#pragma unroll
        for (int i = 0; i < 5; i++) {
            float4 t = qrow[i];
            q[4 * i + 0] = t.x; q[4 * i + 1] = t.y;
            q[4 * i + 2] = t.z; q[4 * i + 3] = t.w;
        }
        ull y2[10];
#pragma unroll
        for (int j = 0; j < 10; j++) y2[j] = pack2(0.0f, 0.0f);
        float nrm = 0.0f;
#pragma unroll
        for (int m = 0; m < H_DIM; m++) {
            ull qq = pack2(q[m], q[m]);
#pragma unroll
            for (int j = 0; j < 10; j++) fma2(y2[j], qq, kvs2[m * 10 + j]);
            nrm = fmaf(q[m], kss[m], nrm);
        }
        float inv = 1.0f / fmaf(scale, nrm, (float)B_DIM);
        float* arow = attn_s + tid * H_DIM;
#pragma unroll
        for (int j = 0; j < 10; j++) {
            float2 f = unpack2(y2[j]);
            arow[2 * j] = fmaf(scale, f.x, vss[2 * j]) * inv;
            arow[2 * j + 1] = fmaf(scale, f.y, vss[2 * j + 1]) * inv;
        }
    }
    __syncthreads();

    int g = w >> 1;
#pragma unroll 1
    for (int rr = 0; rr < 64; rr++) {
        int rowInBlk = g * 64 + rr;
        const float* arow = attn_s + rowInBlk * H_DIM;
        ull a0 = bpr.x, a1 = bpr.y;
#pragma unroll
        for (int h = 0; h < H_DIM; h++) {
            float a = arow[h];
            ull aa = pack2(a, a);
            fma2(a0, aa, wx[h]);
            fma2(a1, aa, wy[h]);
        }
        size_t r = (size_t)(n0 + rowInBlk) * L_DIM + l;
        ulonglong2* st = (ulonglong2*)(out + r * D_EMB + half * 128 + lane * 4);
        *st = make_ulonglong2(a0, a1);
    }
}

// ---------------- launch ------------------------------------------------------
extern "C" void kernel_launch(void* const* d_in, const int* in_sizes, int n_in,
                              void* d_out, int out_size) {
    const float* key   = (const float*)d_in[0];
    const float* value = (const float*)d_in[1];
    const float* query = (const float*)d_in[2];
    const float* Wk    = (const float*)d_in[3];
    const float* bk    = (const float*)d_in[4];
    const float* Wq    = (const float*)d_in[5];
    const float* bq    = (const float*)d_in[6];
    const float* Wv    = (const float*)d_in[7];
    const float* bv    = (const float*)d_in[8];
    const float* Wp    = (const float*)d_in[9];
    const float* bp    = (const float*)d_in[10];
    float* out = (float*)d_out;

    float *qs_p, *ks_p, *vs_p;
    cudaGetSymbolAddress((void**)&qs_p, g_qs);
    cudaGetSymbolAddress((void**)&ks_p, g_ks);
    cudaGetSymbolAddress((void**)&vs_p, g_vs);

    const int PROJ_SMEM = 20608 + P_WARPS * XBUF_WARP * 4;  // 20608+20480=41088
    cudaFuncSetAttribute(proj_kernel, cudaFuncAttributeMaxDynamicSharedMemorySize,
                         PROJ_SMEM);

    zero_kernel<<<100, 256>>>();

    const int PROJ_BLOCKS = R_TOT / P_RPB;  // 1024
    proj_kernel<<<PROJ_BLOCKS, P_THREADS, PROJ_SMEM>>>(query, Wq, bq, qs_p, 0);
    proj_kernel<<<PROJ_BLOCKS, P_THREADS, PROJ_SMEM>>>(key,   Wk, bk, ks_p, 2);
    proj_kernel<<<PROJ_BLOCKS, P_THREADS, PROJ_SMEM>>>(value, Wv, bv, vs_p, -1);

    kvs_kernel<<<dim3(16, 64), 512>>>();

    final_kernel<<<dim3(16, 64), 256>>>(Wp, bp, out);
}